// round 11
// baseline (speedup 1.0000x reference)
#include <cuda_runtime.h>
#include <cuda_bf16.h>
#include <cstdint>

// Problem constants
#define B_    32
#define N_    512
#define D_    1024
#define H_    16
#define HD_   64
#define SEG_  64
#define M_TOT (B_ * N_)                   // 16384
#define OUT_ELEMS   (M_TOT * D_)          // 16,777,216
#define ATTN_ELEMS  (B_ * H_ * N_ * SEG_) // 16,777,216

// -------- Scratch (allocation-free), 16B aligned --------
__device__ __align__(16) __nv_bfloat16 g_ahi[M_TOT * D_];   // A-split / recv-split
__device__ __align__(16) __nv_bfloat16 g_alo[M_TOT * D_];
__device__ __align__(16) __nv_bfloat16 g_qhi[M_TOT * D_];   // q-split (gemm1 out)
__device__ __align__(16) __nv_bfloat16 g_qlo[M_TOT * D_];
__device__ __align__(16) __nv_bfloat16 g_wthi[D_ * D_];
__device__ __align__(16) __nv_bfloat16 g_wtlo[D_ * D_];

// ===========================================================================
// Helpers (baseline PTX only)
// ===========================================================================
__device__ __forceinline__ uint32_t smem_u32(const void* p) {
    uint32_t a;
    asm("{ .reg .u64 t; cvta.to.shared.u64 t, %1; cvt.u32.u64 %0, t; }"
        : "=r"(a) : "l"(p));
    return a;
}
#define CP_ASYNC16(dst_u32, src_ptr) \
    asm volatile("cp.async.cg.shared.global [%0], [%1], 16;" \
                 :: "r"(dst_u32), "l"(src_ptr) : "memory")
#define CP_COMMIT()  asm volatile("cp.async.commit_group;" ::: "memory")
#define CP_WAIT(n)   asm volatile("cp.async.wait_group %0;" :: "n"(n) : "memory")

__device__ __forceinline__ void ldsm_x4(uint32_t* r, uint32_t addr) {
    asm volatile("ldmatrix.sync.aligned.m8n8.x4.shared.b16 {%0,%1,%2,%3}, [%4];"
                 : "=r"(r[0]), "=r"(r[1]), "=r"(r[2]), "=r"(r[3]) : "r"(addr));
}
__device__ __forceinline__ void ldsm_x2(uint32_t* r, uint32_t addr) {
    asm volatile("ldmatrix.sync.aligned.m8n8.x2.shared.b16 {%0,%1}, [%2];"
                 : "=r"(r[0]), "=r"(r[1]) : "r"(addr));
}
__device__ __forceinline__ void ldsm_x2t(uint32_t* r, uint32_t addr) {
    asm volatile("ldmatrix.sync.aligned.m8n8.x2.trans.shared.b16 {%0,%1}, [%2];"
                 : "=r"(r[0]), "=r"(r[1]) : "r"(addr));
}

// m16n8k16 bf16 MMA, fp32 accumulate
__device__ __forceinline__ void mma16816(float* c, const uint32_t* a, const uint32_t* b) {
    asm volatile(
        "mma.sync.aligned.m16n8k16.row.col.f32.bf16.bf16.f32 "
        "{%0,%1,%2,%3}, {%4,%5,%6,%7}, {%8,%9}, {%0,%1,%2,%3};"
        : "+f"(c[0]), "+f"(c[1]), "+f"(c[2]), "+f"(c[3])
        : "r"(a[0]), "r"(a[1]), "r"(a[2]), "r"(a[3]), "r"(b[0]), "r"(b[1]));
}

__device__ __forceinline__ void split2(float x, float y, uint32_t& hi, uint32_t& lo) {
    __nv_bfloat16 hx = __float2bfloat16(x), hy = __float2bfloat16(y);
    __nv_bfloat162 h2, l2;
    h2.x = hx; h2.y = hy;
    l2.x = __float2bfloat16(x - __bfloat162float(hx));
    l2.y = __float2bfloat16(y - __bfloat162float(hy));
    hi = *reinterpret_cast<uint32_t*>(&h2);
    lo = *reinterpret_cast<uint32_t*>(&l2);
}

// ===========================================================================
// Conversion kernels
// ===========================================================================
__global__ __launch_bounds__(256) void split_kernel(
    const float* __restrict__ x, __nv_bfloat16* __restrict__ hi,
    __nv_bfloat16* __restrict__ lo, int n4)
{
    int i = blockIdx.x * blockDim.x + threadIdx.x;
    if (i >= n4) return;
    float4 v = reinterpret_cast<const float4*>(x)[i];
    uint32_t h01, l01, h23, l23;
    split2(v.x, v.y, h01, l01);
    split2(v.z, v.w, h23, l23);
    reinterpret_cast<uint2*>(hi)[i] = make_uint2(h01, h23);
    reinterpret_cast<uint2*>(lo)[i] = make_uint2(l01, l23);
}

__global__ __launch_bounds__(256) void transpose_split(
    const float* __restrict__ W, __nv_bfloat16* __restrict__ Thi,
    __nv_bfloat16* __restrict__ Tlo)
{
    __shared__ float tile[32][33];
    int nx = blockIdx.x * 32 + threadIdx.x;
    #pragma unroll
    for (int i = 0; i < 4; i++) {
        int ky = blockIdx.y * 32 + threadIdx.y + i * 8;
        tile[threadIdx.y + i * 8][threadIdx.x] = W[(size_t)ky * D_ + nx];
    }
    __syncthreads();
    int ko = blockIdx.y * 32 + threadIdx.x;
    #pragma unroll
    for (int i = 0; i < 4; i++) {
        int no = blockIdx.x * 32 + threadIdx.y + i * 8;
        float v = tile[threadIdx.x][threadIdx.y + i * 8];
        __nv_bfloat16 h = __float2bfloat16(v);
        size_t idx = (size_t)no * D_ + ko;
        Thi[idx] = h;
        Tlo[idx] = __float2bfloat16(v - __bfloat162float(h));
    }
}

// ===========================================================================
// Tensor-core GEMM (round-9 geometry + 3-stage pipeline):
//   C[M,1024] = (Ahi+Alo) @ Wt^T + bias,  Wt stored [N][K]
//   128x128 CTA tile, 8 warps (2m x 4n) of 64x32. KC=16.
//   3 stages, cp.async wait_group 1 -> loads run a full chunk ahead.
// ===========================================================================
#define KC      16
#define NCH     (D_ / KC)        // 64
#define SKB     48               // smem row pitch bytes
#define MAT_B   (128 * SKB)      // 6144
#define BUF_B   (4 * MAT_B)      // 24576
#define NSTAGE  3
#define SMEM_SZ (NSTAGE * BUF_B) // 73728

__global__ __launch_bounds__(256) void gemm_mma(
    const __nv_bfloat16* __restrict__ Ahi, const __nv_bfloat16* __restrict__ Alo,
    const __nv_bfloat16* __restrict__ Bhi, const __nv_bfloat16* __restrict__ Blo,
    const float* __restrict__ bias, float* __restrict__ Cf,
    __nv_bfloat16* __restrict__ Chi, __nv_bfloat16* __restrict__ Clo)
{
    extern __shared__ __align__(16) char smem[];
    const uint32_t sb = smem_u32(smem);
    const int tid  = threadIdx.x;
    const int wid  = tid >> 5;
    const int lane = tid & 31;
    const int warp_m = wid & 1;
    const int warp_n = wid >> 1;
    const int row0 = blockIdx.y * 128;
    const int col0 = blockIdx.x * 128;
    const int g    = lane >> 2;
    // ldmatrix lane-address components
    const uint32_t a_lrow = (uint32_t)(warp_m * 64 + (lane & 15)) * SKB + ((lane >> 4) * 16);
    const uint32_t b_lrow = (uint32_t)(warp_n * 32 + (lane & 7)) * SKB + (((lane >> 3) & 1) * 16);

    const __nv_bfloat16* mats[4] = {Ahi, Alo, Bhi, Blo};

    float acc[4][4][4];
    #pragma unroll
    for (int mt = 0; mt < 4; mt++)
        #pragma unroll
        for (int nt = 0; nt < 4; nt++)
            #pragma unroll
            for (int j = 0; j < 4; j++) acc[mt][nt][j] = 0.f;

    const int ld_r = tid >> 1;
    const int ld_c = (tid & 1) * 16;
    auto issue_chunk = [&](int kc, int buf) {
        const int k0 = kc * KC;
        const uint32_t sbase = sb + buf * BUF_B;
        #pragma unroll
        for (int m = 0; m < 4; m++) {
            const int base0 = (m < 2) ? row0 : col0;
            const __nv_bfloat16* src =
                mats[m] + (size_t)(base0 + ld_r) * D_ + k0 + (ld_c >> 1);
            CP_ASYNC16(sbase + m * MAT_B + ld_r * SKB + ld_c, src);
        }
    };

    auto compute_chunk = [&](int buf) {
        const uint32_t sbase = sb + buf * BUF_B;
        uint32_t ah[4][4], al[4][4], bh[4][2], bl[4][2];
        #pragma unroll
        for (int mt = 0; mt < 4; mt++) {
            ldsm_x4(ah[mt], sbase + 0 * MAT_B + a_lrow + mt * 16 * SKB);
            ldsm_x4(al[mt], sbase + 1 * MAT_B + a_lrow + mt * 16 * SKB);
        }
        #pragma unroll
        for (int nt = 0; nt < 4; nt++) {
            ldsm_x2(bh[nt], sbase + 2 * MAT_B + b_lrow + nt * 8 * SKB);
            ldsm_x2(bl[nt], sbase + 3 * MAT_B + b_lrow + nt * 8 * SKB);
        }
        #pragma unroll
        for (int mt = 0; mt < 4; mt++)
            #pragma unroll
            for (int nt = 0; nt < 4; nt++) {
                mma16816(acc[mt][nt], ah[mt], bh[nt]);
                mma16816(acc[mt][nt], ah[mt], bl[nt]);
                mma16816(acc[mt][nt], al[mt], bh[nt]);
            }
    };

    // ---- 3-stage pipeline: compute(i) only requires chunk i; chunk i+1
    //      stays in flight across the whole iteration (wait_group 1) ----
    issue_chunk(0, 0); CP_COMMIT();
    issue_chunk(1, 1); CP_COMMIT();
    for (int i = 0; i < NCH; i++) {
        CP_WAIT(1);                    // chunk i landed; i+1 may still fly
        __syncthreads();               // stage (i+2)%3's old readers are done
        if (i + 2 < NCH) issue_chunk(i + 2, (i + 2) % NSTAGE);
        CP_COMMIT();                   // unconditional: keeps group count aligned
        compute_chunk(i % NSTAGE);
    }

    // ---- epilogue ----
    const int cbase = col0 + warp_n * 32 + (lane & 3) * 2;
    #pragma unroll
    for (int mt = 0; mt < 4; mt++) {
        int r = row0 + warp_m * 64 + mt * 16 + g;
        #pragma unroll
        for (int nt = 0; nt < 4; nt++) {
            int c = cbase + nt * 8;
            float2 bv = *reinterpret_cast<const float2*>(bias + c);
            float x0 = acc[mt][nt][0] + bv.x, y0 = acc[mt][nt][1] + bv.y;
            float x1 = acc[mt][nt][2] + bv.x, y1 = acc[mt][nt][3] + bv.y;
            if (Cf) {
                *reinterpret_cast<float2*>(Cf + (size_t)r * D_ + c) = make_float2(x0, y0);
                *reinterpret_cast<float2*>(Cf + (size_t)(r + 8) * D_ + c) = make_float2(x1, y1);
            } else {
                uint32_t h0, l0, h1, l1;
                split2(x0, y0, h0, l0);
                split2(x1, y1, h1, l1);
                *reinterpret_cast<uint32_t*>(Chi + (size_t)r * D_ + c) = h0;
                *reinterpret_cast<uint32_t*>(Clo + (size_t)r * D_ + c) = l0;
                *reinterpret_cast<uint32_t*>(Chi + (size_t)(r + 8) * D_ + c) = h1;
                *reinterpret_cast<uint32_t*>(Clo + (size_t)(r + 8) * D_ + c) = l1;
            }
        }
    }
}

// ===========================================================================
// Middle stage (unchanged — 78us, on prediction)
// ===========================================================================
#define RP    144
#define RMAT  (64 * RP)
#define RQHI  0
#define RQLO  RMAT
#define RRHI  (2 * RMAT)
#define RRLO  (3 * RMAT)
#define RSMEM (4 * RMAT)         // 36864

__global__ __launch_bounds__(128) void router_mma(
    const float* __restrict__ router,
    const __nv_bfloat16* __restrict__ Qhi, const __nv_bfloat16* __restrict__ Qlo,
    float* __restrict__ attn_out,
    __nv_bfloat16* __restrict__ Rvhi, __nv_bfloat16* __restrict__ Rvlo)
{
    extern __shared__ __align__(16) char rs[];
    const uint32_t sb = smem_u32(rs);
    const int n   = blockIdx.x;
    const int mt  = blockIdx.y;
    const int tid = threadIdx.x;
    const int w   = tid >> 5;
    const int lane = tid & 31;
    const int g   = lane >> 2;
    const int tg  = lane & 3;

    for (int idx = tid; idx < SEG_ * 16; idx += 128) {
        int s = idx >> 4, d4 = (idx & 15) * 4;
        float4 v = *reinterpret_cast<const float4*>(
            router + ((size_t)s * N_ + n) * HD_ + d4);
        uint32_t h01, l01, h23, l23;
        split2(v.x, v.y, h01, l01);
        split2(v.z, v.w, h23, l23);
        uint32_t off = s * RP + d4 * 2;
        *reinterpret_cast<uint32_t*>(rs + RRHI + off)     = h01;
        *reinterpret_cast<uint32_t*>(rs + RRHI + off + 4) = h23;
        *reinterpret_cast<uint32_t*>(rs + RRLO + off)     = l01;
        *reinterpret_cast<uint32_t*>(rs + RRLO + off + 4) = l23;
    }
    for (int idx = tid; idx < 64 * 8; idx += 128) {
        int r = idx >> 3, c8 = (idx & 7) * 8;
        int mg = mt * 64 + r;
        size_t gbase = ((size_t)(mg >> 4) * N_ + n) * D_ + (mg & 15) * HD_ + c8;
        *reinterpret_cast<uint4*>(rs + RQHI + r * RP + c8 * 2) =
            *reinterpret_cast<const uint4*>(Qhi + gbase);
        *reinterpret_cast<uint4*>(rs + RQLO + r * RP + c8 * 2) =
            *reinterpret_cast<const uint4*>(Qlo + gbase);
    }
    __syncthreads();

    float S[8][4];
    #pragma unroll
    for (int j = 0; j < 8; j++)
        #pragma unroll
        for (int q = 0; q < 4; q++) S[j][q] = 0.f;

    const uint32_t a_lrow = (uint32_t)(w * 16 + (lane & 15)) * RP + ((lane >> 4) * 16);
    const uint32_t b_lrow = (uint32_t)(lane & 7) * RP + (((lane >> 3) & 1) * 16);

    #pragma unroll
    for (int t = 0; t < 4; t++) {
        uint32_t ah[4], al[4];
        ldsm_x4(ah, sb + RQHI + a_lrow + t * 32);
        ldsm_x4(al, sb + RQLO + a_lrow + t * 32);
        #pragma unroll
        for (int j = 0; j < 8; j++) {
            uint32_t bh[2], bl[2];
            ldsm_x2(bh, sb + RRHI + b_lrow + j * 8 * RP + t * 32);
            ldsm_x2(bl, sb + RRLO + b_lrow + j * 8 * RP + t * 32);
            mma16816(S[j], ah, bh);
            mma16816(S[j], ah, bl);
            mma16816(S[j], al, bh);
        }
    }

    float m0 = S[0][0], m1 = S[0][2];
    #pragma unroll
    for (int j = 0; j < 8; j++) {
        m0 = fmaxf(m0, fmaxf(S[j][0], S[j][1]));
        m1 = fmaxf(m1, fmaxf(S[j][2], S[j][3]));
    }
    m0 = fmaxf(m0, __shfl_xor_sync(0xffffffffu, m0, 1));
    m0 = fmaxf(m0, __shfl_xor_sync(0xffffffffu, m0, 2));
    m1 = fmaxf(m1, __shfl_xor_sync(0xffffffffu, m1, 1));
    m1 = fmaxf(m1, __shfl_xor_sync(0xffffffffu, m1, 2));
    float s0 = 0.f, s1 = 0.f;
    #pragma unroll
    for (int j = 0; j < 8; j++) {
        S[j][0] = __expf(S[j][0] - m0); s0 += S[j][0];
        S[j][1] = __expf(S[j][1] - m0); s0 += S[j][1];
        S[j][2] = __expf(S[j][2] - m1); s1 += S[j][2];
        S[j][3] = __expf(S[j][3] - m1); s1 += S[j][3];
    }
    s0 += __shfl_xor_sync(0xffffffffu, s0, 1);
    s0 += __shfl_xor_sync(0xffffffffu, s0, 2);
    s1 += __shfl_xor_sync(0xffffffffu, s1, 1);
    s1 += __shfl_xor_sync(0xffffffffu, s1, 2);
    float inv0 = 1.f / s0, inv1 = 1.f / s1;
    #pragma unroll
    for (int j = 0; j < 8; j++) {
        S[j][0] *= inv0; S[j][1] *= inv0;
        S[j][2] *= inv1; S[j][3] *= inv1;
    }

    const int mg0 = mt * 64 + w * 16 + g;
    const int mg1 = mg0 + 8;

    if (attn_out) {
        float* a0p = attn_out + ((size_t)mg0 * N_ + n) * SEG_ + tg * 2;
        float* a1p = attn_out + ((size_t)mg1 * N_ + n) * SEG_ + tg * 2;
        #pragma unroll
        for (int j = 0; j < 8; j++) {
            *reinterpret_cast<float2*>(a0p + j * 8) = make_float2(S[j][0], S[j][1]);
            *reinterpret_cast<float2*>(a1p + j * 8) = make_float2(S[j][2], S[j][3]);
        }
    }

    float O[8][4];
    #pragma unroll
    for (int j = 0; j < 8; j++)
        #pragma unroll
        for (int q = 0; q < 4; q++) O[j][q] = 0.f;

    const uint32_t bt_lrow = (uint32_t)(lane & 15) * RP;
    #pragma unroll
    for (int t = 0; t < 4; t++) {
        uint32_t fh[4], fl[4];
        split2(S[2*t][0],   S[2*t][1],   fh[0], fl[0]);
        split2(S[2*t][2],   S[2*t][3],   fh[1], fl[1]);
        split2(S[2*t+1][0], S[2*t+1][1], fh[2], fl[2]);
        split2(S[2*t+1][2], S[2*t+1][3], fh[3], fl[3]);
        #pragma unroll
        for (int j = 0; j < 8; j++) {
            uint32_t bh[2], bl[2];
            ldsm_x2t(bh, sb + RRHI + (t * 16) * RP + bt_lrow + j * 16);
            ldsm_x2t(bl, sb + RRLO + (t * 16) * RP + bt_lrow + j * 16);
            mma16816(O[j], fh, bh);
            mma16816(O[j], fh, bl);
            mma16816(O[j], fl, bh);
        }
    }

    size_t r0base = ((size_t)(mg0 >> 4) * N_ + n) * D_ + (mg0 & 15) * HD_ + tg * 2;
    size_t r1base = ((size_t)(mg1 >> 4) * N_ + n) * D_ + (mg1 & 15) * HD_ + tg * 2;
    #pragma unroll
    for (int j = 0; j < 8; j++) {
        uint32_t h0, l0, h1, l1;
        split2(O[j][0], O[j][1], h0, l0);
        split2(O[j][2], O[j][3], h1, l1);
        *reinterpret_cast<uint32_t*>(Rvhi + r0base + j * 8) = h0;
        *reinterpret_cast<uint32_t*>(Rvlo + r0base + j * 8) = l0;
        *reinterpret_cast<uint32_t*>(Rvhi + r1base + j * 8) = h1;
        *reinterpret_cast<uint32_t*>(Rvlo + r1base + j * 8) = l1;
    }
}

// ===========================================================================
// Launch
// ===========================================================================
extern "C" void kernel_launch(void* const* d_in, const int* in_sizes, int n_in,
                              void* d_out, int out_size) {
    const float* query  = (const float*)d_in[0];
    const float* router = (const float*)d_in[3];
    const float* Wq     = (const float*)d_in[4];
    const float* bq     = (const float*)d_in[5];
    const float* Wo     = (const float*)d_in[10];
    const float* bo     = (const float*)d_in[11];
    float* out = (float*)d_out;

    __nv_bfloat16 *ahi, *alo, *qhi, *qlo, *wthi, *wtlo;
    cudaGetSymbolAddress((void**)&ahi,  g_ahi);
    cudaGetSymbolAddress((void**)&alo,  g_alo);
    cudaGetSymbolAddress((void**)&qhi,  g_qhi);
    cudaGetSymbolAddress((void**)&qlo,  g_qlo);
    cudaGetSymbolAddress((void**)&wthi, g_wthi);
    cudaGetSymbolAddress((void**)&wtlo, g_wtlo);

    cudaFuncSetAttribute(gemm_mma,
                         cudaFuncAttributeMaxDynamicSharedMemorySize, SMEM_SZ);

    float* attn_out = (out_size >= (int)(OUT_ELEMS + ATTN_ELEMS))
                      ? out + OUT_ELEMS : nullptr;

    dim3 tgrid(32, 32), tblk(32, 8);
    dim3 ggrid(D_ / 128, M_TOT / 128);   // (8, 128)
    int n4 = OUT_ELEMS / 4;

    // 1) Q = query @ Wq + bq  -> split bf16 directly
    split_kernel<<<(n4 + 255) / 256, 256>>>(query, ahi, alo, n4);
    transpose_split<<<tgrid, tblk>>>(Wq, wthi, wtlo);
    gemm_mma<<<ggrid, 256, SMEM_SZ>>>(ahi, alo, wthi, wtlo, bq,
                                      nullptr, qhi, qlo);

    // 2) router attention: attn fp32 + recv split bf16
    router_mma<<<dim3(N_, (B_ * H_) / 64), 128, RSMEM>>>(
        router, qhi, qlo, attn_out, ahi, alo);

    // 3) output = recv @ Wo + bo  (fp32 out)
    transpose_split<<<tgrid, tblk>>>(Wo, wthi, wtlo);
    gemm_mma<<<ggrid, 256, SMEM_SZ>>>(ahi, alo, wthi, wtlo, bo,
                                      out, nullptr, nullptr);
}

// round 12
// speedup vs baseline: 1.6578x; 1.6578x over previous
#include <cuda_runtime.h>
#include <cuda_bf16.h>
#include <cstdint>

// Problem constants
#define B_    32
#define N_    512
#define D_    1024
#define H_    16
#define HD_   64
#define SEG_  64
#define M_TOT (B_ * N_)                   // 16384
#define OUT_ELEMS   (M_TOT * D_)          // 16,777,216
#define ATTN_ELEMS  (B_ * H_ * N_ * SEG_) // 16,777,216

// -------- Scratch (allocation-free), 16B aligned --------
__device__ __align__(16) __nv_bfloat16 g_ahi[M_TOT * D_];   // A-split / recv-split
__device__ __align__(16) __nv_bfloat16 g_alo[M_TOT * D_];
__device__ __align__(16) __nv_bfloat16 g_qhi[M_TOT * D_];   // q-split (gemm1 out)
__device__ __align__(16) __nv_bfloat16 g_qlo[M_TOT * D_];
__device__ __align__(16) uint32_t      g_wp[D_ * D_];       // W^T packed {hi|lo<<16}

// ===========================================================================
// Helpers (baseline PTX only)
// ===========================================================================
__device__ __forceinline__ uint32_t smem_u32(const void* p) {
    uint32_t a;
    asm("{ .reg .u64 t; cvta.to.shared.u64 t, %1; cvt.u32.u64 %0, t; }"
        : "=r"(a) : "l"(p));
    return a;
}
#define CP_ASYNC16(dst_u32, src_ptr) \
    asm volatile("cp.async.cg.shared.global [%0], [%1], 16;" \
                 :: "r"(dst_u32), "l"(src_ptr) : "memory")
#define CP_COMMIT()  asm volatile("cp.async.commit_group;" ::: "memory")
#define CP_WAIT(n)   asm volatile("cp.async.wait_group %0;" :: "n"(n) : "memory")

__device__ __forceinline__ void ldsm_x4(uint32_t* r, uint32_t addr) {
    asm volatile("ldmatrix.sync.aligned.m8n8.x4.shared.b16 {%0,%1,%2,%3}, [%4];"
                 : "=r"(r[0]), "=r"(r[1]), "=r"(r[2]), "=r"(r[3]) : "r"(addr));
}
__device__ __forceinline__ void ldsm_x2(uint32_t* r, uint32_t addr) {
    asm volatile("ldmatrix.sync.aligned.m8n8.x2.shared.b16 {%0,%1}, [%2];"
                 : "=r"(r[0]), "=r"(r[1]) : "r"(addr));
}
__device__ __forceinline__ void ldsm_x2t(uint32_t* r, uint32_t addr) {
    asm volatile("ldmatrix.sync.aligned.m8n8.x2.trans.shared.b16 {%0,%1}, [%2];"
                 : "=r"(r[0]), "=r"(r[1]) : "r"(addr));
}

// m16n8k16 bf16 MMA, fp32 accumulate
__device__ __forceinline__ void mma16816(float* c, const uint32_t* a, const uint32_t* b) {
    asm volatile(
        "mma.sync.aligned.m16n8k16.row.col.f32.bf16.bf16.f32 "
        "{%0,%1,%2,%3}, {%4,%5,%6,%7}, {%8,%9}, {%0,%1,%2,%3};"
        : "+f"(c[0]), "+f"(c[1]), "+f"(c[2]), "+f"(c[3])
        : "r"(a[0]), "r"(a[1]), "r"(a[2]), "r"(a[3]), "r"(b[0]), "r"(b[1]));
}

__device__ __forceinline__ void split2(float x, float y, uint32_t& hi, uint32_t& lo) {
    __nv_bfloat16 hx = __float2bfloat16(x), hy = __float2bfloat16(y);
    __nv_bfloat162 h2, l2;
    h2.x = hx; h2.y = hy;
    l2.x = __float2bfloat16(x - __bfloat162float(hx));
    l2.y = __float2bfloat16(y - __bfloat162float(hy));
    hi = *reinterpret_cast<uint32_t*>(&h2);
    lo = *reinterpret_cast<uint32_t*>(&l2);
}

// ===========================================================================
// Conversion kernels
// ===========================================================================
__global__ __launch_bounds__(256) void split_kernel(
    const float* __restrict__ x, __nv_bfloat16* __restrict__ hi,
    __nv_bfloat16* __restrict__ lo, int n4)
{
    int i = blockIdx.x * blockDim.x + threadIdx.x;
    if (i >= n4) return;
    float4 v = reinterpret_cast<const float4*>(x)[i];
    uint32_t h01, l01, h23, l23;
    split2(v.x, v.y, h01, l01);
    split2(v.z, v.w, h23, l23);
    reinterpret_cast<uint2*>(hi)[i] = make_uint2(h01, h23);
    reinterpret_cast<uint2*>(lo)[i] = make_uint2(l01, l23);
}

// W[K][N] fp32 -> Wp[N][K] uint32 {bf16 hi | bf16 lo << 16} (transpose + pack)
__global__ __launch_bounds__(256) void transpose_pack(
    const float* __restrict__ W, uint32_t* __restrict__ Wp)
{
    __shared__ float tile[32][33];
    int nx = blockIdx.x * 32 + threadIdx.x;
    #pragma unroll
    for (int i = 0; i < 4; i++) {
        int ky = blockIdx.y * 32 + threadIdx.y + i * 8;
        tile[threadIdx.y + i * 8][threadIdx.x] = W[(size_t)ky * D_ + nx];
    }
    __syncthreads();
    int ko = blockIdx.y * 32 + threadIdx.x;
    #pragma unroll
    for (int i = 0; i < 4; i++) {
        int no = blockIdx.x * 32 + threadIdx.y + i * 8;
        float v = tile[threadIdx.x][threadIdx.y + i * 8];
        __nv_bfloat16 h = __float2bfloat16(v);
        __nv_bfloat16 l = __float2bfloat16(v - __bfloat162float(h));
        uint32_t hu = *reinterpret_cast<uint16_t*>(&h);
        uint32_t lu = *reinterpret_cast<uint16_t*>(&l);
        Wp[(size_t)no * D_ + ko] = hu | (lu << 16);
    }
}

// ===========================================================================
// Tensor-core GEMM (round-9 A-pipeline; B direct from global, packed):
//   C[M,1024] = (Ahi+Alo) @ Wt^T + bias,  Wp stored [N][K] packed words.
//   128x128 CTA tile, 8 warps (2m x 4n) of 64x32. KC=16, double buffer.
//   B fragments: LDG.64 (prefetched 1 iter ahead) + PRMT unpack. No B smem.
// ===========================================================================
#define KC      16
#define NCH     (D_ / KC)        // 64
#define SKB     48               // smem row pitch bytes
#define MAT_B   (128 * SKB)      // 6144
#define BUF_B   (2 * MAT_B)      // 12288 (A hi + A lo only)
#define SMEM_SZ (2 * BUF_B)      // 24576

__global__ __launch_bounds__(256, 2) void gemm_mma(
    const __nv_bfloat16* __restrict__ Ahi, const __nv_bfloat16* __restrict__ Alo,
    const uint32_t* __restrict__ Wp,
    const float* __restrict__ bias, float* __restrict__ Cf,
    __nv_bfloat16* __restrict__ Chi, __nv_bfloat16* __restrict__ Clo)
{
    extern __shared__ __align__(16) char smem[];
    const uint32_t sb = smem_u32(smem);
    const int tid  = threadIdx.x;
    const int wid  = tid >> 5;
    const int lane = tid & 31;
    const int warp_m = wid & 1;
    const int warp_n = wid >> 1;
    const int row0 = blockIdx.y * 128;
    const int col0 = blockIdx.x * 128;
    const int g    = lane >> 2;
    const int tg   = lane & 3;
    const uint32_t a_lrow = (uint32_t)(warp_m * 64 + (lane & 15)) * SKB + ((lane >> 4) * 16);

    // B base pointer (words): row = col0 + warp_n*32 + g, col = tg*2
    const uint32_t* bw = Wp + (size_t)(col0 + warp_n * 32 + g) * D_ + tg * 2;

    float acc[4][4][4];
    #pragma unroll
    for (int mt = 0; mt < 4; mt++)
        #pragma unroll
        for (int nt = 0; nt < 4; nt++)
            #pragma unroll
            for (int j = 0; j < 4; j++) acc[mt][nt][j] = 0.f;

    // ---- A cp.async: 2 matrices x 128 rows x 32B; 1 x 16B per thread per mat
    const int ld_r = tid >> 1;
    const int ld_c = (tid & 1) * 16;
    auto issue_chunk = [&](int kc, int buf) {
        const int k0 = kc * KC;
        const uint32_t sbase = sb + buf * BUF_B;
        const __nv_bfloat16* srcH = Ahi + (size_t)(row0 + ld_r) * D_ + k0 + (ld_c >> 1);
        const __nv_bfloat16* srcL = Alo + (size_t)(row0 + ld_r) * D_ + k0 + (ld_c >> 1);
        CP_ASYNC16(sbase + 0 * MAT_B + ld_r * SKB + ld_c, srcH);
        CP_ASYNC16(sbase + 1 * MAT_B + ld_r * SKB + ld_c, srcL);
    };

    // ---- prologue: A chunk 0 in flight; B iter-0 words prefetched ----
    issue_chunk(0, 0); CP_COMMIT();
    uint2 pv[4][2];
    #pragma unroll
    for (int nt = 0; nt < 4; nt++) {
        pv[nt][0] = *reinterpret_cast<const uint2*>(bw + nt * 8 * D_);
        pv[nt][1] = *reinterpret_cast<const uint2*>(bw + nt * 8 * D_ + 8);
    }

    for (int i = 0; i < NCH; i++) {
        CP_WAIT(0);
        __syncthreads();
        if (i + 1 < NCH) { issue_chunk(i + 1, (i + 1) & 1); CP_COMMIT(); }

        // unpack prefetched B words -> hi/lo fragments (prefetch regs freed)
        uint32_t bh[4][2], bl[4][2];
        #pragma unroll
        for (int nt = 0; nt < 4; nt++) {
            bh[nt][0] = __byte_perm(pv[nt][0].x, pv[nt][0].y, 0x5410);
            bl[nt][0] = __byte_perm(pv[nt][0].x, pv[nt][0].y, 0x7632);
            bh[nt][1] = __byte_perm(pv[nt][1].x, pv[nt][1].y, 0x5410);
            bl[nt][1] = __byte_perm(pv[nt][1].x, pv[nt][1].y, 0x7632);
        }
        // prefetch B for next iteration (hidden under this iteration's MMAs)
        if (i + 1 < NCH) {
            const int koff = (i + 1) * KC;
            #pragma unroll
            for (int nt = 0; nt < 4; nt++) {
                pv[nt][0] = *reinterpret_cast<const uint2*>(bw + koff + nt * 8 * D_);
                pv[nt][1] = *reinterpret_cast<const uint2*>(bw + koff + nt * 8 * D_ + 8);
            }
        }

        // A fragments streamed per m-tile; 3-term split MMAs
        const uint32_t sbase = sb + (i & 1) * BUF_B;
        #pragma unroll
        for (int mt = 0; mt < 4; mt++) {
            uint32_t ah[4], al[4];
            ldsm_x4(ah, sbase + 0 * MAT_B + a_lrow + mt * 16 * SKB);
            ldsm_x4(al, sbase + 1 * MAT_B + a_lrow + mt * 16 * SKB);
            #pragma unroll
            for (int nt = 0; nt < 4; nt++) {
                mma16816(acc[mt][nt], ah, bh[nt]);
                mma16816(acc[mt][nt], ah, bl[nt]);
                mma16816(acc[mt][nt], al, bh[nt]);
            }
        }
    }

    // ---- epilogue ----
    const int cbase = col0 + warp_n * 32 + tg * 2;
    #pragma unroll
    for (int mt = 0; mt < 4; mt++) {
        int r = row0 + warp_m * 64 + mt * 16 + g;
        #pragma unroll
        for (int nt = 0; nt < 4; nt++) {
            int c = cbase + nt * 8;
            float2 bv = *reinterpret_cast<const float2*>(bias + c);
            float x0 = acc[mt][nt][0] + bv.x, y0 = acc[mt][nt][1] + bv.y;
            float x1 = acc[mt][nt][2] + bv.x, y1 = acc[mt][nt][3] + bv.y;
            if (Cf) {
                *reinterpret_cast<float2*>(Cf + (size_t)r * D_ + c) = make_float2(x0, y0);
                *reinterpret_cast<float2*>(Cf + (size_t)(r + 8) * D_ + c) = make_float2(x1, y1);
            } else {
                uint32_t h0, l0, h1, l1;
                split2(x0, y0, h0, l0);
                split2(x1, y1, h1, l1);
                *reinterpret_cast<uint32_t*>(Chi + (size_t)r * D_ + c) = h0;
                *reinterpret_cast<uint32_t*>(Clo + (size_t)r * D_ + c) = l0;
                *reinterpret_cast<uint32_t*>(Chi + (size_t)(r + 8) * D_ + c) = h1;
                *reinterpret_cast<uint32_t*>(Clo + (size_t)(r + 8) * D_ + c) = l1;
            }
        }
    }
}

// ===========================================================================
// Middle stage (unchanged — 78us champion config)
// ===========================================================================
#define RP    144
#define RMAT  (64 * RP)
#define RQHI  0
#define RQLO  RMAT
#define RRHI  (2 * RMAT)
#define RRLO  (3 * RMAT)
#define RSMEM (4 * RMAT)         // 36864

__global__ __launch_bounds__(128) void router_mma(
    const float* __restrict__ router,
    const __nv_bfloat16* __restrict__ Qhi, const __nv_bfloat16* __restrict__ Qlo,
    float* __restrict__ attn_out,
    __nv_bfloat16* __restrict__ Rvhi, __nv_bfloat16* __restrict__ Rvlo)
{
    extern __shared__ __align__(16) char rs[];
    const uint32_t sb = smem_u32(rs);
    const int n   = blockIdx.x;
    const int mt  = blockIdx.y;
    const int tid = threadIdx.x;
    const int w   = tid >> 5;
    const int lane = tid & 31;
    const int g   = lane >> 2;
    const int tg  = lane & 3;

    for (int idx = tid; idx < SEG_ * 16; idx += 128) {
        int s = idx >> 4, d4 = (idx & 15) * 4;
        float4 v = *reinterpret_cast<const float4*>(
            router + ((size_t)s * N_ + n) * HD_ + d4);
        uint32_t h01, l01, h23, l23;
        split2(v.x, v.y, h01, l01);
        split2(v.z, v.w, h23, l23);
        uint32_t off = s * RP + d4 * 2;
        *reinterpret_cast<uint32_t*>(rs + RRHI + off)     = h01;
        *reinterpret_cast<uint32_t*>(rs + RRHI + off + 4) = h23;
        *reinterpret_cast<uint32_t*>(rs + RRLO + off)     = l01;
        *reinterpret_cast<uint32_t*>(rs + RRLO + off + 4) = l23;
    }
    for (int idx = tid; idx < 64 * 8; idx += 128) {
        int r = idx >> 3, c8 = (idx & 7) * 8;
        int mg = mt * 64 + r;
        size_t gbase = ((size_t)(mg >> 4) * N_ + n) * D_ + (mg & 15) * HD_ + c8;
        *reinterpret_cast<uint4*>(rs + RQHI + r * RP + c8 * 2) =
            *reinterpret_cast<const uint4*>(Qhi + gbase);
        *reinterpret_cast<uint4*>(rs + RQLO + r * RP + c8 * 2) =
            *reinterpret_cast<const uint4*>(Qlo + gbase);
    }
    __syncthreads();

    float S[8][4];
    #pragma unroll
    for (int j = 0; j < 8; j++)
        #pragma unroll
        for (int q = 0; q < 4; q++) S[j][q] = 0.f;

    const uint32_t a_lrow = (uint32_t)(w * 16 + (lane & 15)) * RP + ((lane >> 4) * 16);
    const uint32_t b_lrow = (uint32_t)(lane & 7) * RP + (((lane >> 3) & 1) * 16);

    #pragma unroll
    for (int t = 0; t < 4; t++) {
        uint32_t ah[4], al[4];
        ldsm_x4(ah, sb + RQHI + a_lrow + t * 32);
        ldsm_x4(al, sb + RQLO + a_lrow + t * 32);
        #pragma unroll
        for (int j = 0; j < 8; j++) {
            uint32_t bh[2], bl[2];
            ldsm_x2(bh, sb + RRHI + b_lrow + j * 8 * RP + t * 32);
            ldsm_x2(bl, sb + RRLO + b_lrow + j * 8 * RP + t * 32);
            mma16816(S[j], ah, bh);
            mma16816(S[j], ah, bl);
            mma16816(S[j], al, bh);
        }
    }

    float m0 = S[0][0], m1 = S[0][2];
    #pragma unroll
    for (int j = 0; j < 8; j++) {
        m0 = fmaxf(m0, fmaxf(S[j][0], S[j][1]));
        m1 = fmaxf(m1, fmaxf(S[j][2], S[j][3]));
    }
    m0 = fmaxf(m0, __shfl_xor_sync(0xffffffffu, m0, 1));
    m0 = fmaxf(m0, __shfl_xor_sync(0xffffffffu, m0, 2));
    m1 = fmaxf(m1, __shfl_xor_sync(0xffffffffu, m1, 1));
    m1 = fmaxf(m1, __shfl_xor_sync(0xffffffffu, m1, 2));
    float s0 = 0.f, s1 = 0.f;
    #pragma unroll
    for (int j = 0; j < 8; j++) {
        S[j][0] = __expf(S[j][0] - m0); s0 += S[j][0];
        S[j][1] = __expf(S[j][1] - m0); s0 += S[j][1];
        S[j][2] = __expf(S[j][2] - m1); s1 += S[j][2];
        S[j][3] = __expf(S[j][3] - m1); s1 += S[j][3];
    }
    s0 += __shfl_xor_sync(0xffffffffu, s0, 1);
    s0 += __shfl_xor_sync(0xffffffffu, s0, 2);
    s1 += __shfl_xor_sync(0xffffffffu, s1, 1);
    s1 += __shfl_xor_sync(0xffffffffu, s1, 2);
    float inv0 = 1.f / s0, inv1 = 1.f / s1;
    #pragma unroll
    for (int j = 0; j < 8; j++) {
        S[j][0] *= inv0; S[j][1] *= inv0;
        S[j][2] *= inv1; S[j][3] *= inv1;
    }

    const int mg0 = mt * 64 + w * 16 + g;
    const int mg1 = mg0 + 8;

    if (attn_out) {
        float* a0p = attn_out + ((size_t)mg0 * N_ + n) * SEG_ + tg * 2;
        float* a1p = attn_out + ((size_t)mg1 * N_ + n) * SEG_ + tg * 2;
        #pragma unroll
        for (int j = 0; j < 8; j++) {
            *reinterpret_cast<float2*>(a0p + j * 8) = make_float2(S[j][0], S[j][1]);
            *reinterpret_cast<float2*>(a1p + j * 8) = make_float2(S[j][2], S[j][3]);
        }
    }

    float O[8][4];
    #pragma unroll
    for (int j = 0; j < 8; j++)
        #pragma unroll
        for (int q = 0; q < 4; q++) O[j][q] = 0.f;

    const uint32_t bt_lrow = (uint32_t)(lane & 15) * RP;
    #pragma unroll
    for (int t = 0; t < 4; t++) {
        uint32_t fh[4], fl[4];
        split2(S[2*t][0],   S[2*t][1],   fh[0], fl[0]);
        split2(S[2*t][2],   S[2*t][3],   fh[1], fl[1]);
        split2(S[2*t+1][0], S[2*t+1][1], fh[2], fl[2]);
        split2(S[2*t+1][2], S[2*t+1][3], fh[3], fl[3]);
        #pragma unroll
        for (int j = 0; j < 8; j++) {
            uint32_t bh[2], bl[2];
            ldsm_x2t(bh, sb + RRHI + (t * 16) * RP + bt_lrow + j * 16);
            ldsm_x2t(bl, sb + RRLO + (t * 16) * RP + bt_lrow + j * 16);
            mma16816(O[j], fh, bh);
            mma16816(O[j], fh, bl);
            mma16816(O[j], fl, bh);
        }
    }

    size_t r0base = ((size_t)(mg0 >> 4) * N_ + n) * D_ + (mg0 & 15) * HD_ + tg * 2;
    size_t r1base = ((size_t)(mg1 >> 4) * N_ + n) * D_ + (mg1 & 15) * HD_ + tg * 2;
    #pragma unroll
    for (int j = 0; j < 8; j++) {
        uint32_t h0, l0, h1, l1;
        split2(O[j][0], O[j][1], h0, l0);
        split2(O[j][2], O[j][3], h1, l1);
        *reinterpret_cast<uint32_t*>(Rvhi + r0base + j * 8) = h0;
        *reinterpret_cast<uint32_t*>(Rvlo + r0base + j * 8) = l0;
        *reinterpret_cast<uint32_t*>(Rvhi + r1base + j * 8) = h1;
        *reinterpret_cast<uint32_t*>(Rvlo + r1base + j * 8) = l1;
    }
}

// ===========================================================================
// Launch
// ===========================================================================
extern "C" void kernel_launch(void* const* d_in, const int* in_sizes, int n_in,
                              void* d_out, int out_size) {
    const float* query  = (const float*)d_in[0];
    const float* router = (const float*)d_in[3];
    const float* Wq     = (const float*)d_in[4];
    const float* bq     = (const float*)d_in[5];
    const float* Wo     = (const float*)d_in[10];
    const float* bo     = (const float*)d_in[11];
    float* out = (float*)d_out;

    __nv_bfloat16 *ahi, *alo, *qhi, *qlo;
    uint32_t *wp;
    cudaGetSymbolAddress((void**)&ahi, g_ahi);
    cudaGetSymbolAddress((void**)&alo, g_alo);
    cudaGetSymbolAddress((void**)&qhi, g_qhi);
    cudaGetSymbolAddress((void**)&qlo, g_qlo);
    cudaGetSymbolAddress((void**)&wp,  g_wp);

    float* attn_out = (out_size >= (int)(OUT_ELEMS + ATTN_ELEMS))
                      ? out + OUT_ELEMS : nullptr;

    dim3 tgrid(32, 32), tblk(32, 8);
    dim3 ggrid(D_ / 128, M_TOT / 128);   // (8, 128)
    int n4 = OUT_ELEMS / 4;

    // 1) Q = query @ Wq + bq  -> split bf16 directly
    split_kernel<<<(n4 + 255) / 256, 256>>>(query, ahi, alo, n4);
    transpose_pack<<<tgrid, tblk>>>(Wq, wp);
    gemm_mma<<<ggrid, 256, SMEM_SZ>>>(ahi, alo, wp, bq,
                                      nullptr, qhi, qlo);

    // 2) router attention: attn fp32 + recv split bf16
    router_mma<<<dim3(N_, (B_ * H_) / 64), 128, RSMEM>>>(
        router, qhi, qlo, attn_out, ahi, alo);

    // 3) output = recv @ Wo + bo  (fp32 out)
    transpose_pack<<<tgrid, tblk>>>(Wo, wp);
    gemm_mma<<<ggrid, 256, SMEM_SZ>>>(ahi, alo, wp, bo,
                                      out, nullptr, nullptr);
}